// round 1
// baseline (speedup 1.0000x reference)
#include <cuda_runtime.h>

#define TSTEPS 100
#define BATCH  512
#define NIN    700
#define NHID   512
#define NOUT   20
#define ALPHA  0.9f
#define BETA   0.8f
#define THR    1.0f

// ---------------- scratch (static device globals; no runtime allocation) ----------------
__device__ float g_cur0[(size_t)TSTEPS * BATCH * NHID];     // 100 MB: layer0 pre-activations, all t
__device__ float g_xbuf[4][2][BATCH * NHID];                // spike outputs, layers 0..3, double-buffered by t parity
__device__ float g_synH[4][BATCH * NHID];                   // syn state layers 0..3
__device__ float g_memH[4][BATCH * NHID];                   // mem state layers 0..3
__device__ float g_syn4[BATCH * NOUT];
__device__ float g_mem4[BATCH * NOUT];

__device__ __forceinline__ void snn_update(float cur, float& syn, float& mem, float& x) {
    float reset = (mem > THR) ? THR : 0.0f;   // reset from PREVIOUS mem
    syn = ALPHA * syn + cur;
    mem = BETA * mem + syn - reset;
    x = (mem > THR) ? 1.0f : 0.0f;
}

// ---------------- fp32 tile GEMM: C[128x64] = A(row-major, MxK) * W(row-major, NxK)^T ----
// 128 threads, 8x8 microtile, k-major smem with padded stride, double-buffered.
template<bool GUARDK>
__device__ __forceinline__ void gemm_tile_128x64(
    const float* __restrict__ A,      // already offset to row m0
    const float* __restrict__ W,      // already offset to row n0
    int lda, int ldb, int Kdim,
    float acc[8][8], int tid,
    float As[2][16][132], float Bs[2][16][68])
{
    const int ntiles = (Kdim + 15) >> 4;

    auto load_tile = [&](int kt, int buf) {
        const int k0 = kt << 4;
        // A: 128 rows x 16 k = 512 float4; 4 per thread
        #pragma unroll
        for (int i = 0; i < 4; i++) {
            int q  = tid + (i << 7);
            int m  = q >> 2;
            int kk = (q & 3) << 2;
            int kg = k0 + kk;
            float4 v;
            if (!GUARDK || (kg + 3 < Kdim)) {
                v = *(const float4*)(A + (size_t)m * lda + kg);
            } else {
                v.x = (kg + 0 < Kdim) ? A[(size_t)m * lda + kg + 0] : 0.0f;
                v.y = (kg + 1 < Kdim) ? A[(size_t)m * lda + kg + 1] : 0.0f;
                v.z = (kg + 2 < Kdim) ? A[(size_t)m * lda + kg + 2] : 0.0f;
                v.w = (kg + 3 < Kdim) ? A[(size_t)m * lda + kg + 3] : 0.0f;
            }
            As[buf][kk + 0][m] = v.x;
            As[buf][kk + 1][m] = v.y;
            As[buf][kk + 2][m] = v.z;
            As[buf][kk + 3][m] = v.w;
        }
        // B: 64 rows x 16 k = 256 float4; 2 per thread
        #pragma unroll
        for (int i = 0; i < 2; i++) {
            int q  = tid + (i << 7);
            int n  = q >> 2;
            int kk = (q & 3) << 2;
            int kg = k0 + kk;
            float4 v;
            if (!GUARDK || (kg + 3 < Kdim)) {
                v = *(const float4*)(W + (size_t)n * ldb + kg);
            } else {
                v.x = (kg + 0 < Kdim) ? W[(size_t)n * ldb + kg + 0] : 0.0f;
                v.y = (kg + 1 < Kdim) ? W[(size_t)n * ldb + kg + 1] : 0.0f;
                v.z = (kg + 2 < Kdim) ? W[(size_t)n * ldb + kg + 2] : 0.0f;
                v.w = (kg + 3 < Kdim) ? W[(size_t)n * ldb + kg + 3] : 0.0f;
            }
            Bs[buf][kk + 0][n] = v.x;
            Bs[buf][kk + 1][n] = v.y;
            Bs[buf][kk + 2][n] = v.z;
            Bs[buf][kk + 3][n] = v.w;
        }
    };

    load_tile(0, 0);
    __syncthreads();
    const int tx = tid & 7, ty = tid >> 3;

    for (int kt = 0; kt < ntiles; kt++) {
        int cur = kt & 1;
        if (kt + 1 < ntiles) load_tile(kt + 1, cur ^ 1);   // prefetch into other buffer
        #pragma unroll
        for (int kk = 0; kk < 16; kk++) {
            float a[8], b[8];
            *(float4*)&a[0] = *(const float4*)&As[cur][kk][ty * 8 + 0];
            *(float4*)&a[4] = *(const float4*)&As[cur][kk][ty * 8 + 4];
            *(float4*)&b[0] = *(const float4*)&Bs[cur][kk][tx * 8 + 0];
            *(float4*)&b[4] = *(const float4*)&Bs[cur][kk][tx * 8 + 4];
            #pragma unroll
            for (int i = 0; i < 8; i++)
                #pragma unroll
                for (int j = 0; j < 8; j++)
                    acc[i][j] = fmaf(a[i], b[j], acc[i][j]);
        }
        __syncthreads();
    }
}

// ---------------- zero all recurrent state (runs every graph replay) ----------------
__global__ void snn_zero_state() {
    int i = blockIdx.x * blockDim.x + threadIdx.x;
    const int n1 = 4 * BATCH * NHID;
    if (i < n1) {
        (&g_synH[0][0])[i] = 0.0f;
        (&g_memH[0][0])[i] = 0.0f;
    }
    if (i < BATCH * NOUT) {
        g_syn4[i] = 0.0f;
        g_mem4[i] = 0.0f;
    }
}

// ---------------- layer-0 big GEMM: g_cur0 = data @ W0^T (bias added later) ----------------
__global__ void __launch_bounds__(128) snn_gemm0(
    const float* __restrict__ data, const float* __restrict__ W0)
{
    __shared__ float As[2][16][132];
    __shared__ float Bs[2][16][68];
    const int tid = threadIdx.x;
    const int m0 = blockIdx.x * 128;   // over T*B = 51200
    const int n0 = blockIdx.y * 64;    // over NHID = 512

    float acc[8][8];
    #pragma unroll
    for (int i = 0; i < 8; i++)
        #pragma unroll
        for (int j = 0; j < 8; j++) acc[i][j] = 0.0f;

    gemm_tile_128x64<true>(data + (size_t)m0 * NIN, W0 + (size_t)n0 * NIN,
                           NIN, NIN, NIN, acc, tid, As, Bs);

    const int tx = tid & 7, ty = tid >> 3;
    #pragma unroll
    for (int i = 0; i < 8; i++) {
        size_t row = (size_t)(m0 + ty * 8 + i) * NHID + n0 + tx * 8;
        #pragma unroll
        for (int jj = 0; jj < 2; jj++) {
            float4 v = make_float4(acc[i][jj * 4 + 0], acc[i][jj * 4 + 1],
                                   acc[i][jj * 4 + 2], acc[i][jj * 4 + 3]);
            *(float4*)(g_cur0 + row + jj * 4) = v;
        }
    }
}

// ---------------- wavefront step kernel ----------------
// step s covers: L0 update at t=s (blocks 0..127), L1..L3 GEMM+update at t=s-i
// (32 blocks each, 128..223), L4 GEMM+update+output at t=s-4 (blocks 224..239).
#define STEP_BLOCKS 240

__global__ void __launch_bounds__(128) snn_step(
    int s,
    const float* __restrict__ b0,
    const float* __restrict__ W1, const float* __restrict__ b1,
    const float* __restrict__ W2, const float* __restrict__ b2,
    const float* __restrict__ W3, const float* __restrict__ b3,
    const float* __restrict__ W4, const float* __restrict__ b4,
    float* __restrict__ out)
{
    __shared__ float As[2][16][132];
    __shared__ float Bs[2][16][68];
    const int bid = blockIdx.x;
    const int tid = threadIdx.x;

    if (bid < 128) {
        // ---- layer 0 elementwise update at t = s ----
        int t = s;
        if (t >= TSTEPS) return;
        const float* cur0 = g_cur0 + (size_t)t * BATCH * NHID;
        float* xout = g_xbuf[0][t & 1];
        float* syn = g_synH[0];
        float* mem = g_memH[0];
        int base = bid * 2048;                 // 2048 elems per block
        #pragma unroll
        for (int i = 0; i < 4; i++) {
            int e = base + (tid + (i << 7)) * 4;
            float4 c  = *(const float4*)(cur0 + e);
            float4 bv = *(const float4*)(b0 + (e & (NHID - 1)));
            float4 s4 = *(float4*)(syn + e);
            float4 m4 = *(float4*)(mem + e);
            float4 x4;
            snn_update(c.x + bv.x, s4.x, m4.x, x4.x);
            snn_update(c.y + bv.y, s4.y, m4.y, x4.y);
            snn_update(c.z + bv.z, s4.z, m4.z, x4.z);
            snn_update(c.w + bv.w, s4.w, m4.w, x4.w);
            *(float4*)(syn + e)  = s4;
            *(float4*)(mem + e)  = m4;
            *(float4*)(xout + e) = x4;
        }
        return;
    }

    if (bid < 224) {
        // ---- hidden layers 1..3: 512x512x512 GEMM + fused SNN update ----
        int seg   = (bid - 128) >> 5;      // 0..2
        int blk   = (bid - 128) & 31;      // 0..31
        int layer = 1 + seg;
        int t = s - layer;
        if (t < 0 || t >= TSTEPS) return;

        const float* Wt; const float* bt;
        if (layer == 1)      { Wt = W1; bt = b1; }
        else if (layer == 2) { Wt = W2; bt = b2; }
        else                 { Wt = W3; bt = b3; }

        const float* Ain = g_xbuf[layer - 1][t & 1];
        float* syn  = g_synH[layer];
        float* mem  = g_memH[layer];
        float* xout = g_xbuf[layer][t & 1];

        int m0 = (blk >> 3) * 128;   // 4 row groups
        int n0 = (blk & 7) * 64;     // 8 col groups

        float acc[8][8];
        #pragma unroll
        for (int i = 0; i < 8; i++)
            #pragma unroll
            for (int j = 0; j < 8; j++) acc[i][j] = 0.0f;

        gemm_tile_128x64<false>(Ain + (size_t)m0 * NHID, Wt + (size_t)n0 * NHID,
                                NHID, NHID, NHID, acc, tid, As, Bs);

        const int tx = tid & 7, ty = tid >> 3;
        #pragma unroll
        for (int i = 0; i < 8; i++) {
            int m = m0 + ty * 8 + i;
            #pragma unroll
            for (int jj = 0; jj < 2; jj++) {
                int n = n0 + tx * 8 + jj * 4;
                size_t idx = (size_t)m * NHID + n;
                float4 s4 = *(float4*)(syn + idx);
                float4 m4 = *(float4*)(mem + idx);
                float4 bv = *(const float4*)(bt + n);
                float4 x4;
                snn_update(acc[i][jj * 4 + 0] + bv.x, s4.x, m4.x, x4.x);
                snn_update(acc[i][jj * 4 + 1] + bv.y, s4.y, m4.y, x4.y);
                snn_update(acc[i][jj * 4 + 2] + bv.z, s4.z, m4.z, x4.z);
                snn_update(acc[i][jj * 4 + 3] + bv.w, s4.w, m4.w, x4.w);
                *(float4*)(syn + idx)  = s4;
                *(float4*)(mem + idx)  = m4;
                *(float4*)(xout + idx) = x4;
            }
        }
        return;
    }

    {
        // ---- layer 4: 512x20x512 GEMM + update + write output spikes ----
        int t = s - 4;
        if (t < 0 || t >= TSTEPS) return;
        int b4id = bid - 224;              // 0..15, 32 batch rows each
        int wid  = tid >> 5;
        int lane = tid & 31;
        const float* xin = g_xbuf[3][t & 1];

        #pragma unroll 1
        for (int r = 0; r < 8; r++) {
            int m = b4id * 32 + wid * 8 + r;
            const float4* xrow = (const float4*)(xin + (size_t)m * NHID);
            float acc[NOUT];
            #pragma unroll
            for (int j = 0; j < NOUT; j++) acc[j] = 0.0f;

            #pragma unroll
            for (int it = 0; it < 4; it++) {
                int kk = lane + it * 32;            // float4 index 0..127
                float4 xv = xrow[kk];
                #pragma unroll
                for (int j = 0; j < NOUT; j++) {
                    float4 wv = *(const float4*)(W4 + (size_t)j * NHID + kk * 4);
                    acc[j] += xv.x * wv.x + xv.y * wv.y + xv.z * wv.z + xv.w * wv.w;
                }
            }
            #pragma unroll
            for (int j = 0; j < NOUT; j++) {
                float v = acc[j];
                v += __shfl_xor_sync(0xffffffffu, v, 16);
                v += __shfl_xor_sync(0xffffffffu, v, 8);
                v += __shfl_xor_sync(0xffffffffu, v, 4);
                v += __shfl_xor_sync(0xffffffffu, v, 2);
                v += __shfl_xor_sync(0xffffffffu, v, 1);
                acc[j] = v;
            }
            if (lane < NOUT) {
                int j = lane;
                int idx = m * NOUT + j;
                float sv = g_syn4[idx], mv = g_mem4[idx], xv;
                snn_update(acc[j] + b4[j], sv, mv, xv);
                g_syn4[idx] = sv;
                g_mem4[idx] = mv;
                out[(size_t)t * BATCH * NOUT + idx] = xv;
            }
        }
        return;
    }
}

// ---------------- launch ----------------
extern "C" void kernel_launch(void* const* d_in, const int* in_sizes, int n_in,
                              void* d_out, int out_size) {
    const float* data = (const float*)d_in[0];
    const float* W0 = (const float*)d_in[1];
    const float* b0 = (const float*)d_in[2];
    const float* W1 = (const float*)d_in[3];
    const float* b1 = (const float*)d_in[4];
    const float* W2 = (const float*)d_in[5];
    const float* b2 = (const float*)d_in[6];
    const float* W3 = (const float*)d_in[7];
    const float* b3 = (const float*)d_in[8];
    const float* W4 = (const float*)d_in[9];
    const float* b4 = (const float*)d_in[10];
    float* out = (float*)d_out;

    // reset recurrent state (must run every replay)
    snn_zero_state<<<4096, 256>>>();

    // layer-0 pre-activations for all timesteps: one big GEMM
    dim3 g0(51200 / 128, NHID / 64);
    snn_gemm0<<<g0, 128>>>(data, W0);

    // wavefront over (layer, time): step s handles layer i at t = s - i
    for (int s = 0; s < TSTEPS + 4; s++) {
        snn_step<<<STEP_BLOCKS, 128>>>(s, b0, W1, b1, W2, b2, W3, b3, W4, b4, out);
    }
}